// round 5
// baseline (speedup 1.0000x reference)
#include <cuda_runtime.h>

#define NVOX     400000
#define K27      27
#define VB       16
#define NBATCH   (NVOX / VB)            // 25000 exact
#define WSTRIDE  36                     // floats per (g,k,co-pair) row; 144B stride
#define WS_FLOATS (108 * 8 * WSTRIDE)   // 31104 floats = 124,416 B
#define SMEM_BYTES (WS_FLOATS * 4)

__device__ int g_ctr;

// A-chunk Cq (4 input channels) x interleaved weight quads Wa, Wb:
// Wa = {w[2j][c0], w[2j][c1], w[2j+1][c0], w[2j+1][c1]}
#define DO4(Cq, Wa, Wb)                                                       \
    a0 = fmaf(Cq.x, Wa.x, a0); a1 = fmaf(Cq.x, Wa.y, a1);                     \
    a0 = fmaf(Cq.y, Wa.z, a0); a1 = fmaf(Cq.y, Wa.w, a1);                     \
    a0 = fmaf(Cq.z, Wb.x, a0); a1 = fmaf(Cq.z, Wb.y, a1);                     \
    a0 = fmaf(Cq.w, Wb.z, a0); a1 = fmaf(Cq.w, Wb.w, a1);

__global__ void __launch_bounds__(512, 1)
subm_conv_kernel(const float* __restrict__ feat,
                 const float* __restrict__ wgt,
                 const float* __restrict__ bias,
                 const int*   __restrict__ nbr,
                 float*       __restrict__ out)
{
    extern __shared__ float ws[];   // transposed/interleaved weights only

    const int tid  = threadIdx.x;
    const int lane = tid & 31;
    const unsigned FULL = 0xffffffffu;

    // Weight smem fill: src [g][k][ci][co] (co fastest == linear t).
    // dst row = (g*27+k)*8 + (co>>1), float index 2*ci + (co&1).
    for (int t = tid; t < 108 * 256; t += 512) {
        int co = t & 15, ci = (t >> 4) & 15, gk = t >> 8;
        ws[(gk * 8 + (co >> 1)) * WSTRIDE + 2 * ci + (co & 1)] = wgt[t];
    }
    __syncthreads();

    const int g = lane >> 3;            // group owned by this lane
    const int r = lane & 7;             // co-pair owned by this lane
    const int wofs = g * (K27 * 8 * WSTRIDE) + r * WSTRIDE;
    const float b0 = bias[2 * lane];
    const float b1 = bias[2 * lane + 1];
    const float4* __restrict__ feat4 = (const float4*)feat;

    for (;;) {
        int batch;
        if (lane == 0) batch = atomicAdd(&g_ctr, 1);
        batch = __shfl_sync(FULL, batch, 0);
        if (batch >= NBATCH) break;
        const int vb = batch * VB;

        // Lane l (<27) holds neighbor index for offset l of each batch voxel.
        int myidx[VB];
        unsigned vbits = 0;
#pragma unroll
        for (int v = 0; v < VB; ++v) {
            int ii = -1;
            if (lane < K27) ii = nbr[(vb + v) * K27 + lane];
            myidx[v] = ii;
            vbits |= (unsigned)(ii >= 0) << v;
        }
        unsigned km = __ballot_sync(FULL, vbits != 0);

        float acc0[VB], acc1[VB];
#pragma unroll
        for (int v = 0; v < VB; ++v) { acc0[v] = b0; acc1[v] = b1; }

        while (km) {
            const int k = __ffs(km) - 1;
            km &= km - 1;
            const unsigned bm = __shfl_sync(FULL, vbits, k);   // warp-uniform

            // Weights for (g, k, co-pair r): 8 LDS.128, conflict-free phases.
            const float4* wp = (const float4*)(ws + wofs + k * (8 * WSTRIDE));
            const float4 W0 = wp[0], W1 = wp[1], W2 = wp[2], W3 = wp[3];
            const float4 W4 = wp[4], W5 = wp[5], W6 = wp[6], W7 = wp[7];

            // Depth-1 pipelined loop over valid voxels; A gathered directly
            // from global (group-broadcast LDG.128, no smem staging).
            float4 P0, P1, P2, P3;
            if (bm & 1u) {
                int idx = __shfl_sync(FULL, myidx[0], k);
                const float4* ap = feat4 + idx * 16 + g * 4;
                P0 = ap[0]; P1 = ap[1]; P2 = ap[2]; P3 = ap[3];
            }
#pragma unroll
            for (int v = 0; v < VB; ++v) {
                float4 C0 = P0, C1 = P1, C2 = P2, C3 = P3;
                if (v + 1 < VB && (bm & (1u << (v + 1)))) {
                    int idx = __shfl_sync(FULL, myidx[v + 1], k);
                    const float4* ap = feat4 + idx * 16 + g * 4;
                    P0 = ap[0]; P1 = ap[1]; P2 = ap[2]; P3 = ap[3];
                }
                if (bm & (1u << v)) {
                    float a0 = acc0[v], a1 = acc1[v];
                    DO4(C0, W0, W1);
                    DO4(C1, W2, W3);
                    DO4(C2, W4, W5);
                    DO4(C3, W6, W7);
                    acc0[v] = a0; acc1[v] = a1;
                }
            }
        }

        // Contiguous 256B float2 stores per voxel row.
#pragma unroll
        for (int v = 0; v < VB; ++v)
            *(float2*)(out + (vb + v) * 64 + 2 * lane) =
                make_float2(acc0[v], acc1[v]);
    }
}

extern "C" void kernel_launch(void* const* d_in, const int* in_sizes, int n_in,
                              void* d_out, int out_size) {
    const float* feat = (const float*)d_in[0];
    const float* wgt  = (const float*)d_in[1];
    const float* bias = (const float*)d_in[2];
    const int*   nbr  = (const int*)d_in[3];
    float* out = (float*)d_out;

    void* ctr = nullptr;
    cudaGetSymbolAddress(&ctr, g_ctr);
    cudaMemsetAsync(ctr, 0, sizeof(int));

    cudaFuncSetAttribute(subm_conv_kernel,
                         cudaFuncAttributeMaxDynamicSharedMemorySize, SMEM_BYTES);
    subm_conv_kernel<<<148, 512, SMEM_BYTES>>>(feat, wgt, bias, nbr, out);
}

// round 8
// speedup vs baseline: 1.1992x; 1.1992x over previous
#include <cuda_runtime.h>

#define NVOX   400000
#define K27    27
#define VB     12
#define NBATCH ((NVOX + VB - 1) / VB)     // 33334 (last batch has 4 voxels)
#define WQUADS (K27 * 8 * 32)             // 6912 float4 = 110,592 B
#define SMEM_BYTES (WQUADS * 16)

__device__ int g_ctr;

// A-scalar (one ci) times the lane's co-quad weights
#define FMA1(as, Wq)                                                          \
    a0 = fmaf(as, Wq.x, a0); a1 = fmaf(as, Wq.y, a1);                         \
    a2 = fmaf(as, Wq.z, a2); a3 = fmaf(as, Wq.w, a3);

__global__ void __launch_bounds__(512, 1)
subm_conv_kernel(const float* __restrict__ feat,
                 const float* __restrict__ wgt,
                 const float* __restrict__ bias,
                 const int*   __restrict__ nbr,
                 float*       __restrict__ out)
{
    extern __shared__ float4 wq[];   // [k][cil(8)][chunk(32)] ; chunk = g*8+s*4+cop
    const int tid  = threadIdx.x;
    const int lane = tid & 31;
    const unsigned FULL = 0xffffffffu;

    // Fill weights. src t = ((g*27+k)*16+ci)*16+co  (co fastest, == linear t)
    for (int t = tid; t < 108 * 256; t += 512) {
        int co = t & 15, ci = (t >> 4) & 15, gk = t >> 8;
        int gg = gk / K27, kk = gk % K27;
        int ss = ci >> 3, cil = ci & 7, cp = co >> 2;
        ((float*)wq)[(((kk * 8 + cil) * 32) + (gg * 8 + ss * 4 + cp)) * 4 + (co & 3)] = wgt[t];
    }
    __syncthreads();

    const int g   = lane >> 3;         // group
    const int s   = (lane >> 2) & 1;   // ci-half
    const int cop = lane & 3;          // co-quad
    const float4 b4 = *(const float4*)(bias + g * 16 + cop * 4);
    const float4* __restrict__ f4 = (const float4*)feat;
    const int aofs = g * 4 + s * 2;    // lane's float4 offset within a feature row

    for (;;) {
        int batch;
        if (lane == 0) batch = atomicAdd(&g_ctr, 1);
        batch = __shfl_sync(FULL, batch, 0);
        if (batch >= NBATCH) break;
        const int vb   = batch * VB;
        const int vcnt = min(VB, NVOX - vb);

        // Lane l (<27) holds neighbor index for offset l of each batch voxel.
        int myidx[VB];
        unsigned vbits = 0;
#pragma unroll
        for (int v = 0; v < VB; ++v) {
            int ii = -1;
            if (lane < K27 && v < vcnt) ii = nbr[(vb + v) * K27 + lane];
            myidx[v] = ii;
            vbits |= (unsigned)(ii >= 0) << v;
        }
        unsigned km = __ballot_sync(FULL, vbits != 0);

        float acc[VB][4];
#pragma unroll
        for (int v = 0; v < VB; ++v) {
            acc[v][0] = 0.f; acc[v][1] = 0.f; acc[v][2] = 0.f; acc[v][3] = 0.f;
        }

        while (km) {
            const int k = __ffs(km) - 1;
            km &= km - 1;
            const unsigned bm = __shfl_sync(FULL, vbits, k);   // warp-uniform

            // Lane's 8 weight quads for (k): 32 contiguous float4 per LDS row,
            // conflict-free 4-phase LDS.128, no padding needed.
            const float4* wp = wq + k * 256 + lane;
            const float4 W0 = wp[0],   W1 = wp[32],  W2 = wp[64],  W3 = wp[96];
            const float4 W4 = wp[128], W5 = wp[160], W6 = wp[192], W7 = wp[224];

            // Depth-1 pipelined loop over batch voxels; A read directly from
            // global: 2x LDG.128 spanning exactly the 256B feature row.
            float4 P0, P1;
            if (bm & 1u) {
                int j = __shfl_sync(FULL, myidx[0], k);
                P0 = f4[j * 16 + aofs];
                P1 = f4[j * 16 + aofs + 1];
            }
#pragma unroll
            for (int v = 0; v < VB; ++v) {
                float4 A0 = P0, A1 = P1;
                if (v + 1 < VB && (bm & (2u << v))) {
                    int j = __shfl_sync(FULL, myidx[v + 1], k);
                    P0 = f4[j * 16 + aofs];
                    P1 = f4[j * 16 + aofs + 1];
                }
                if (bm & (1u << v)) {
                    float a0 = acc[v][0], a1 = acc[v][1], a2 = acc[v][2], a3 = acc[v][3];
                    FMA1(A0.x, W0); FMA1(A0.y, W1); FMA1(A0.z, W2); FMA1(A0.w, W3);
                    FMA1(A1.x, W4); FMA1(A1.y, W5); FMA1(A1.z, W6); FMA1(A1.w, W7);
                    acc[v][0] = a0; acc[v][1] = a1; acc[v][2] = a2; acc[v][3] = a3;
                }
            }
        }

        // Fold the two ci-halves (lanes differing in bit 2) and store.
#pragma unroll
        for (int v = 0; v < VB; ++v) {
            float r0 = acc[v][0] + __shfl_xor_sync(FULL, acc[v][0], 4);
            float r1 = acc[v][1] + __shfl_xor_sync(FULL, acc[v][1], 4);
            float r2 = acc[v][2] + __shfl_xor_sync(FULL, acc[v][2], 4);
            float r3 = acc[v][3] + __shfl_xor_sync(FULL, acc[v][3], 4);
            if (s == 0 && v < vcnt) {
                float4 r = make_float4(r0 + b4.x, r1 + b4.y, r2 + b4.z, r3 + b4.w);
                *(float4*)(out + (vb + v) * 64 + g * 16 + cop * 4) = r;
            }
        }
    }
}

extern "C" void kernel_launch(void* const* d_in, const int* in_sizes, int n_in,
                              void* d_out, int out_size) {
    const float* feat = (const float*)d_in[0];
    const float* wgt  = (const float*)d_in[1];
    const float* bias = (const float*)d_in[2];
    const int*   nbr  = (const int*)d_in[3];
    float* out = (float*)d_out;

    void* ctr = nullptr;
    cudaGetSymbolAddress(&ctr, g_ctr);
    cudaMemsetAsync(ctr, 0, sizeof(int));

    cudaFuncSetAttribute(subm_conv_kernel,
                         cudaFuncAttributeMaxDynamicSharedMemorySize, SMEM_BYTES);
    subm_conv_kernel<<<148, 512, SMEM_BYTES>>>(feat, wgt, bias, nbr, out);
}

// round 10
// speedup vs baseline: 1.3325x; 1.1111x over previous
#include <cuda_runtime.h>

#define NVOX   400000
#define K27    27
#define VB     12
#define NBATCH ((NVOX + VB - 1) / VB)     // 33334 (last batch has 4 voxels)
#define NWARP  12
#define NTHR   (NWARP * 32)
#define WQ_FLOATS (K27 * 8 * 32 * 4)      // 27648 floats = 110,592 B
#define NBUF   3
#define STG_FLOATS (NWARP * NBUF * VB * 64)   // 27648 floats = 110,592 B
#define SMEM_BYTES ((WQ_FLOATS + STG_FLOATS) * 4)   // 221,184 B

#define CP16(dst_u32, src) \
    asm volatile("cp.async.cg.shared.global [%0], [%1], 16;\n" :: "r"(dst_u32), "l"(src))
#define CPCOMMIT() asm volatile("cp.async.commit_group;\n" ::: "memory")
#define CPWAIT(n)  asm volatile("cp.async.wait_group %0;\n" :: "n"(n) : "memory")

// A-scalar (one ci) times the lane's co-quad weights
#define FMA1(as, Wq)                                                          \
    a0 = fmaf(as, Wq.x, a0); a1 = fmaf(as, Wq.y, a1);                         \
    a2 = fmaf(as, Wq.z, a2); a3 = fmaf(as, Wq.w, a3);

__global__ void __launch_bounds__(NTHR, 1)
subm_conv_kernel(const float* __restrict__ feat,
                 const float* __restrict__ wgt,
                 const float* __restrict__ bias,
                 const int*   __restrict__ nbr,
                 float*       __restrict__ out)
{
    extern __shared__ float smem[];
    float4* wq = (float4*)smem;                      // [k][cil(8)][chunk(32)] quads
    float*  stg = smem + WQ_FLOATS;                  // per-warp 3x12-row staging

    const int tid  = threadIdx.x;
    const int lane = tid & 31;
    const int warp = tid >> 5;
    const unsigned FULL = 0xffffffffu;

    // Fill weights. src t = ((g*27+k)*16+ci)*16+co  (co fastest == linear t)
    for (int t = tid; t < 108 * 256; t += NTHR) {
        int co = t & 15, ci = (t >> 4) & 15, gk = t >> 8;
        int gg = gk / K27, kk = gk % K27;
        int cil = ci & 7, ss = ci >> 3, cp = co >> 2;
        smem[(((kk * 8 + cil) * 32) + (gg * 8 + ss * 4 + cp)) * 4 + (co & 3)] = wgt[t];
    }
    __syncthreads();

    const int g   = lane >> 3;          // group
    const int s   = (lane >> 2) & 1;    // ci-half
    const int cop = lane & 3;           // co-quad
    const float4 b4 = *(const float4*)(bias + g * 16 + cop * 4);
    const int aofs = g * 4 + s * 2;     // lane's float4 offset within a 64f row

    float* mystg = stg + warp * (NBUF * VB * 64);
    const unsigned stg_u32 = (unsigned)__cvta_generic_to_shared(mystg);

    for (int batch = blockIdx.x * NWARP + warp; batch < NBATCH;
         batch += gridDim.x * NWARP) {
        const int vb   = batch * VB;
        const int vcnt = min(VB, NVOX - vb);

        // Lane l (<27) holds neighbor index for offset l of each batch voxel.
        int myidx[VB];
        unsigned vbits = 0;
#pragma unroll
        for (int v = 0; v < VB; ++v) {
            int ii = -1;
            if (lane < K27 && v < vcnt) ii = nbr[(vb + v) * K27 + lane];
            myidx[v] = ii;
            vbits |= (unsigned)(ii >= 0) << v;
        }
        const unsigned km = __ballot_sync(FULL, vbits != 0);

        // ---- producer: one commit-group per k-offset (empty when exhausted)
        unsigned pkm = km;
        int pc = 0;
        auto produce_k = [&]() {
            if (pkm) {
                const int kk = __ffs(pkm) - 1;
                pkm &= pkm - 1;
                const unsigned bmp = __shfl_sync(FULL, vbits, kk);
                const unsigned sbuf = stg_u32 + (unsigned)(pc % NBUF) * (VB * 256);
                int rc = 0;
#pragma unroll
                for (int v = 0; v < VB; ++v)
                    if (bmp & (1u << v)) {
                        const int j = __shfl_sync(FULL, myidx[v], kk);
                        if (lane < 16)
                            CP16(sbuf + rc * 256 + lane * 16,
                                 feat + (long long)j * 64 + lane * 4);
                        rc++;
                    }
                pc++;
            }
            CPCOMMIT();
        };
        produce_k(); produce_k(); produce_k();   // 3-deep pipeline prologue

        float acc[VB][4];
#pragma unroll
        for (int v = 0; v < VB; ++v) {
            acc[v][0] = 0.f; acc[v][1] = 0.f; acc[v][2] = 0.f; acc[v][3] = 0.f;
        }

        // ---- consumer
        unsigned ckm = km;
        int cc = 0;
        while (ckm) {
            const int k = __ffs(ckm) - 1;
            ckm &= ckm - 1;
            const unsigned bm = __shfl_sync(FULL, vbits, k);

            CPWAIT(NBUF - 1);     // group cc complete (issued == cc + 3 always)
            __syncwarp();

            // Lane's 8 weight quads for k: 4-phase conflict-optimal LDS.128.
            const float4* wp = wq + k * 256 + lane;
            const float4 W0 = wp[0],   W1 = wp[32],  W2 = wp[64],  W3 = wp[96];
            const float4 W4 = wp[128], W5 = wp[160], W6 = wp[192], W7 = wp[224];

            const float4* buf = (const float4*)(mystg + (cc % NBUF) * (VB * 64));
            int rowc = 0;
#pragma unroll
            for (int v = 0; v < VB; ++v)
                if (bm & (1u << v)) {
                    const float4 A0 = buf[rowc * 16 + aofs];
                    const float4 A1 = buf[rowc * 16 + aofs + 1];
                    rowc++;
                    float a0 = acc[v][0], a1 = acc[v][1];
                    float a2 = acc[v][2], a3 = acc[v][3];
                    FMA1(A0.x, W0); FMA1(A0.y, W1); FMA1(A0.z, W2); FMA1(A0.w, W3);
                    FMA1(A1.x, W4); FMA1(A1.y, W5); FMA1(A1.z, W6); FMA1(A1.w, W7);
                    acc[v][0] = a0; acc[v][1] = a1; acc[v][2] = a2; acc[v][3] = a3;
                }

            cc++;
            produce_k();          // keep pipeline 3 groups ahead
        }
        CPWAIT(0);                // drain (empties) so accounting resets per batch
        __syncwarp();

        // Fold the two ci-halves (lanes differing in bit 2) and store.
#pragma unroll
        for (int v = 0; v < VB; ++v) {
            float r0 = acc[v][0] + __shfl_xor_sync(FULL, acc[v][0], 4);
            float r1 = acc[v][1] + __shfl_xor_sync(FULL, acc[v][1], 4);
            float r2 = acc[v][2] + __shfl_xor_sync(FULL, acc[v][2], 4);
            float r3 = acc[v][3] + __shfl_xor_sync(FULL, acc[v][3], 4);
            if (s == 0 && v < vcnt) {
                float4 r = make_float4(r0 + b4.x, r1 + b4.y, r2 + b4.z, r3 + b4.w);
                *(float4*)(out + (long long)(vb + v) * 64 + g * 16 + cop * 4) = r;
            }
        }
    }
}

extern "C" void kernel_launch(void* const* d_in, const int* in_sizes, int n_in,
                              void* d_out, int out_size) {
    const float* feat = (const float*)d_in[0];
    const float* wgt  = (const float*)d_in[1];
    const float* bias = (const float*)d_in[2];
    const int*   nbr  = (const int*)d_in[3];
    float* out = (float*)d_out;

    cudaFuncSetAttribute(subm_conv_kernel,
                         cudaFuncAttributeMaxDynamicSharedMemorySize, SMEM_BYTES);
    subm_conv_kernel<<<148, NTHR, SMEM_BYTES>>>(feat, wgt, bias, nbr, out);
}

// round 11
// speedup vs baseline: 1.4278x; 1.0716x over previous
#include <cuda_runtime.h>

#define NVOX   400000
#define K27    27
#define VB     12
#define NBATCH ((NVOX + VB - 1) / VB)     // 33334 (last batch has 4 voxels)
#define NWARP  12
#define NTHR   (NWARP * 32)
#define WQ_FLOATS (K27 * 8 * 32 * 4)      // 27648 floats = 110,592 B
#define NBUF   3
#define STG_FLOATS (NWARP * NBUF * VB * 64)   // 27648 floats = 110,592 B
#define SMEM_BYTES ((WQ_FLOATS + STG_FLOATS) * 4)   // 221,184 B

typedef unsigned long long u64;

#define CP16(dst_u32, src) \
    asm volatile("cp.async.cg.shared.global [%0], [%1], 16;\n" :: "r"(dst_u32), "l"(src))
#define CPCOMMIT() asm volatile("cp.async.commit_group;\n" ::: "memory")
#define CPWAIT(n)  asm volatile("cp.async.wait_group %0;\n" :: "n"(n) : "memory")

__device__ __forceinline__ u64 pk2(float lo, float hi) {
    u64 r; asm("mov.b64 %0, {%1, %2};" : "=l"(r) : "f"(lo), "f"(hi)); return r;
}
__device__ __forceinline__ void upk2(float& lo, float& hi, u64 p) {
    asm("mov.b64 {%0, %1}, %2;" : "=f"(lo), "=f"(hi) : "l"(p));
}
#define FMA2(acc, a, b) asm("fma.rn.f32x2 %0, %1, %2, %0;" : "+l"(acc) : "l"(a), "l"(b))
#define ADD2(d, a, b)   asm("add.rn.f32x2 %0, %1, %2;" : "=l"(d) : "l"(a), "l"(b))

// one ci scalar: splat then 2 packed FMAs into the lane's 4 outputs
#define CI1(as, Wlo, Whi) { u64 sp = pk2(as, as); FMA2(p0, sp, Wlo); FMA2(p1, sp, Whi); }

__global__ void __launch_bounds__(NTHR, 1)
subm_conv_kernel(const float* __restrict__ feat,
                 const float* __restrict__ wgt,
                 const float* __restrict__ bias,
                 const int*   __restrict__ nbr,
                 float*       __restrict__ out)
{
    extern __shared__ float smem[];
    float* stg = smem + WQ_FLOATS;

    const int tid  = threadIdx.x;
    const int lane = tid & 31;
    const int warp = tid >> 5;
    const unsigned FULL = 0xffffffffu;

    // Fill weights. src t = ((g*27+k)*16+ci)*16+co  (co fastest == linear t)
    // dst float index: (((kk*8+cil)*32) + (g*8+s*4+cp))*4 + (co&3)
    for (int t = tid; t < 108 * 256; t += NTHR) {
        int co = t & 15, ci = (t >> 4) & 15, gk = t >> 8;
        int gg = gk / K27, kk = gk % K27;
        int cil = ci & 7, ss = ci >> 3, cp = co >> 2;
        smem[(((kk * 8 + cil) * 32) + (gg * 8 + ss * 4 + cp)) * 4 + (co & 3)] = wgt[t];
    }
    __syncthreads();

    const int g   = lane >> 3;          // group
    const int s   = (lane >> 2) & 1;    // ci-half
    const int cop = lane & 3;           // co-quad
    const float4 b4 = *(const float4*)(bias + g * 16 + cop * 4);
    const u64 bP0 = pk2(b4.x, b4.y), bP1 = pk2(b4.z, b4.w);
    const int aofs = g * 4 + s * 2;     // lane's float4 offset within a 64f row

    float* mystg = stg + warp * (NBUF * VB * 64);
    const unsigned stg_u32 = (unsigned)__cvta_generic_to_shared(mystg);
    const int bstride = gridDim.x * NWARP;

    // prefetch first batch's nbr column
    int batch0 = blockIdx.x * NWARP + warp;
    int nxt[VB];
    {
        int vc = min(VB, NVOX - batch0 * VB);
#pragma unroll
        for (int v = 0; v < VB; ++v) {
            nxt[v] = -1;
            if (batch0 < NBATCH && lane < K27 && v < vc)
                nxt[v] = nbr[(batch0 * VB + v) * K27 + lane];
        }
    }

    for (int batch = batch0; batch < NBATCH; batch += bstride) {
        const int vb   = batch * VB;
        const int vcnt = min(VB, NVOX - vb);

        int myidx[VB];
        unsigned vbits = 0;
#pragma unroll
        for (int v = 0; v < VB; ++v) {
            myidx[v] = nxt[v];
            vbits |= (unsigned)(nxt[v] >= 0) << v;
        }
        const unsigned km = __ballot_sync(FULL, vbits != 0);

        // prefetch next batch's nbr column (hides ~LDG latency behind compute)
        const int nb = batch + bstride;
        const int nvc = (nb < NBATCH) ? min(VB, NVOX - nb * VB) : 0;
#pragma unroll
        for (int v = 0; v < VB; ++v) {
            nxt[v] = -1;
            if (lane < K27 && v < nvc)
                nxt[v] = nbr[(nb * VB + v) * K27 + lane];
        }

        // ---- producer: one commit-group per k-offset (empty when exhausted)
        unsigned pkm = km;
        int pc = 0;
        auto produce_k = [&]() {
            if (pkm) {
                const int kk = __ffs(pkm) - 1;
                pkm &= pkm - 1;
                const unsigned bmp = __shfl_sync(FULL, vbits, kk);
                const unsigned sbuf = stg_u32 + (unsigned)(pc % NBUF) * (VB * 256);
                unsigned dst = sbuf + lane * 16;
#pragma unroll
                for (int v = 0; v < VB; ++v)
                    if (bmp & (1u << v)) {
                        const int j = __shfl_sync(FULL, myidx[v], kk);
                        if (lane < 16)
                            CP16(dst, feat + (long long)j * 64 + lane * 4);
                        dst += 256;
                    }
                pc++;
            }
            CPCOMMIT();
        };
        produce_k(); produce_k(); produce_k();

        u64 acc0[VB], acc1[VB];
#pragma unroll
        for (int v = 0; v < VB; ++v) { acc0[v] = 0ull; acc1[v] = 0ull; }

        // ---- consumer
        unsigned ckm = km;
        int cc = 0;
        while (ckm) {
            const int k = __ffs(ckm) - 1;
            ckm &= ckm - 1;
            const unsigned bm = __shfl_sync(FULL, vbits, k);

            // Weight LDS issued BEFORE the wait: latency overlaps cp drain.
            // Quad j = w[ci=s*8+j][co 4cop..4cop+3] -> lo/hi packed co-pairs.
            const ulonglong2* wp = (const ulonglong2*)(smem + k * 1024) + lane;
            const ulonglong2 W0 = wp[0],   W1 = wp[32],  W2 = wp[64],  W3 = wp[96];
            const ulonglong2 W4 = wp[128], W5 = wp[160], W6 = wp[192], W7 = wp[224];

            CPWAIT(NBUF - 1);
            __syncwarp();

            const float4* bp = (const float4*)(mystg + (cc % NBUF) * (VB * 64));
#pragma unroll
            for (int v = 0; v < VB; ++v)
                if (bm & (1u << v)) {
                    const float4 A0 = bp[aofs];
                    const float4 A1 = bp[aofs + 1];
                    bp += 16;
                    u64 p0 = acc0[v], p1 = acc1[v];
                    CI1(A0.x, W0.x, W0.y); CI1(A0.y, W1.x, W1.y);
                    CI1(A0.z, W2.x, W2.y); CI1(A0.w, W3.x, W3.y);
                    CI1(A1.x, W4.x, W4.y); CI1(A1.y, W5.x, W5.y);
                    CI1(A1.z, W6.x, W6.y); CI1(A1.w, W7.x, W7.y);
                    acc0[v] = p0; acc1[v] = p1;
                }

            cc++;
            produce_k();
        }
        CPWAIT(0);
        __syncwarp();

        // Fold ci-halves (lanes differing in bit 2), add bias, store packed.
#pragma unroll
        for (int v = 0; v < VB; ++v) {
            u64 o0 = __shfl_xor_sync(FULL, acc0[v], 4);
            u64 o1 = __shfl_xor_sync(FULL, acc1[v], 4);
            ADD2(o0, o0, acc0[v]);
            ADD2(o1, o1, acc1[v]);
            ADD2(o0, o0, bP0);
            ADD2(o1, o1, bP1);
            if (s == 0 && v < vcnt) {
                float4 r;
                upk2(r.x, r.y, o0);
                upk2(r.z, r.w, o1);
                *(float4*)(out + (long long)(vb + v) * 64 + g * 16 + cop * 4) = r;
            }
        }
    }
}

extern "C" void kernel_launch(void* const* d_in, const int* in_sizes, int n_in,
                              void* d_out, int out_size) {
    const float* feat = (const float*)d_in[0];
    const float* wgt  = (const float*)d_in[1];
    const float* bias = (const float*)d_in[2];
    const int*   nbr  = (const int*)d_in[3];
    float* out = (float*)d_out;

    cudaFuncSetAttribute(subm_conv_kernel,
                         cudaFuncAttributeMaxDynamicSharedMemorySize, SMEM_BYTES);
    subm_conv_kernel<<<148, NTHR, SMEM_BYTES>>>(feat, wgt, bias, nbr, out);
}

// round 13
// speedup vs baseline: 1.5542x; 1.0885x over previous
#include <cuda_runtime.h>

#define NVOX   400000
#define K27    27
#define VB     12
#define NBATCH ((NVOX + VB - 1) / VB)     // 33334
#define NWARP  16
#define NTHR   (NWARP * 32)
#define WQ_FLOATS (K27 * 8 * 32 * 4)      // 27648 floats = 110,592 B
#define NBUF   2
#define STG_FLOATS (NWARP * NBUF * VB * 64)   // 24576 floats = 98,304 B
#define SMEM_BYTES ((WQ_FLOATS + STG_FLOATS) * 4)   // 208,896 B

typedef unsigned long long u64;

#define CP16(dst_u32, src) \
    asm volatile("cp.async.cg.shared.global [%0], [%1], 16;\n" :: "r"(dst_u32), "l"(src))
#define CPCOMMIT() asm volatile("cp.async.commit_group;\n" ::: "memory")
#define CPWAIT(n)  asm volatile("cp.async.wait_group %0;\n" :: "n"(n) : "memory")

__device__ __forceinline__ void upk2(float& lo, float& hi, u64 p) {
    asm("mov.b64 {%0, %1}, %2;" : "=f"(lo), "=f"(hi) : "l"(p));
}
// acc.(lo,hi) += a.(even_ci, odd_ci) * w.(even_ci, odd_ci)  — no splats needed
#define FMA2(acc, a, b) asm("fma.rn.f32x2 %0, %1, %2, %0;" : "+l"(acc) : "l"(a), "l"(b))

__global__ void __launch_bounds__(NTHR, 1)
subm_conv_kernel(const float* __restrict__ feat,
                 const float* __restrict__ wgt,
                 const float* __restrict__ bias,
                 const int*   __restrict__ nbr,
                 float*       __restrict__ out)
{
    extern __shared__ float smem[];
    float* stg = smem + WQ_FLOATS;

    const int tid  = threadIdx.x;
    const int lane = tid & 31;
    const int warp = tid >> 5;
    const unsigned FULL = 0xffffffffu;

    // Weight fill. src t = ((g*27+k)*16+ci)*16+co (co fastest == linear t).
    // dst float4 (k, j=ci>>1, lane=g*8+(co>>1)) =
    //   {w[2j][co0], w[2j+1][co0], w[2j][co1], w[2j+1][co1]}  (co0=2r, co1=2r+1)
    for (int t = tid; t < 108 * 256; t += NTHR) {
        int co = t & 15, ci = (t >> 4) & 15, gk = t >> 8;
        int gg = gk / K27, kk = gk % K27;
        int j = ci >> 1, par = ci & 1, rr = co >> 1, ce = co & 1;
        smem[(((kk * 8 + j) * 32) + (gg * 8 + rr)) * 4 + ce * 2 + par] = wgt[t];
    }
    __syncthreads();

    const int g = lane >> 3;            // group
    const int r = lane & 7;             // co-pair within group
    const float b0 = bias[g * 16 + 2 * r];
    const float b1 = bias[g * 16 + 2 * r + 1];

    float* mystg = stg + warp * (NBUF * VB * 64);
    const unsigned stg_u32 = (unsigned)__cvta_generic_to_shared(mystg);
    const int bstride = gridDim.x * NWARP;

    for (int batch = blockIdx.x * NWARP + warp; batch < NBATCH; batch += bstride) {
        const int vb   = batch * VB;
        const int vcnt = min(VB, NVOX - vb);

        // Lane l (<27) holds neighbor index for offset l of each batch voxel.
        int myidx[VB];
        unsigned vbits = 0;
#pragma unroll
        for (int v = 0; v < VB; ++v) {
            int ii = -1;
            if (lane < K27 && v < vcnt) ii = nbr[(vb + v) * K27 + lane];
            myidx[v] = ii;
            vbits |= (unsigned)(ii >= 0) << v;
        }
        const unsigned km = __ballot_sync(FULL, vbits != 0);

        // ---- producer: one commit-group per k-offset (empty when exhausted)
        unsigned pkm = km;
        int pc = 0;
        auto produce_k = [&]() {
            if (pkm) {
                const int kk = __ffs(pkm) - 1;
                pkm &= pkm - 1;
                const unsigned bmp = __shfl_sync(FULL, vbits, kk);
                unsigned dst = stg_u32 + (unsigned)(pc % NBUF) * (VB * 256) + lane * 16;
#pragma unroll
                for (int v = 0; v < VB; ++v)
                    if (bmp & (1u << v)) {
                        const int j = __shfl_sync(FULL, myidx[v], kk);
                        if (lane < 16)
                            CP16(dst, feat + (long long)j * 64 + lane * 4);
                        dst += 256;
                    }
                pc++;
            }
            CPCOMMIT();
        };
        produce_k(); produce_k();      // 2-deep pipeline prologue

        u64 acc0[VB], acc1[VB];        // (even-ci, odd-ci) partials per output co
#pragma unroll
        for (int v = 0; v < VB; ++v) { acc0[v] = 0ull; acc1[v] = 0ull; }

        // ---- consumer
        unsigned ckm = km;
        int cc = 0;
        while (ckm) {
            const int k = __ffs(ckm) - 1;
            ckm &= ckm - 1;
            const unsigned bm = __shfl_sync(FULL, vbits, k);

            // Weight LDS issued BEFORE the wait (latency overlaps cp drain).
            const ulonglong2* wp = (const ulonglong2*)(smem + k * 1024) + lane;
            const ulonglong2 W0 = wp[0],   W1 = wp[32],  W2 = wp[64],  W3 = wp[96];
            const ulonglong2 W4 = wp[128], W5 = wp[160], W6 = wp[192], W7 = wp[224];

            CPWAIT(NBUF - 1);
            __syncwarp();

            const float* rowp = mystg + (cc % NBUF) * (VB * 64);
#pragma unroll
            for (int v = 0; v < VB; ++v)
                if (bm & (1u << v)) {
                    // Lane reads its group's 64B as 4 packed-ci-pair u64x2.
                    const ulonglong2* ap = (const ulonglong2*)(rowp + g * 16);
                    const ulonglong2 A0 = ap[0], A1 = ap[1];
                    const ulonglong2 A2 = ap[2], A3 = ap[3];
                    rowp += 64;
                    u64 p0 = acc0[v], p1 = acc1[v];
                    FMA2(p0, A0.x, W0.x); FMA2(p1, A0.x, W0.y);
                    FMA2(p0, A0.y, W1.x); FMA2(p1, A0.y, W1.y);
                    FMA2(p0, A1.x, W2.x); FMA2(p1, A1.x, W2.y);
                    FMA2(p0, A1.y, W3.x); FMA2(p1, A1.y, W3.y);
                    FMA2(p0, A2.x, W4.x); FMA2(p1, A2.x, W4.y);
                    FMA2(p0, A2.y, W5.x); FMA2(p1, A2.y, W5.y);
                    FMA2(p0, A3.x, W6.x); FMA2(p1, A3.x, W6.y);
                    FMA2(p0, A3.y, W7.x); FMA2(p1, A3.y, W7.y);
                    acc0[v] = p0; acc1[v] = p1;
                }

            cc++;
            produce_k();
        }
        CPWAIT(0);
        __syncwarp();

        // Epilogue: fold even/odd halves, add bias, contiguous float2 stores.
#pragma unroll
        for (int v = 0; v < VB; ++v)
            if (v < vcnt) {
                float e0, o0, e1, o1;
                upk2(e0, o0, acc0[v]);
                upk2(e1, o1, acc1[v]);
                *(float2*)(out + (long long)(vb + v) * 64 + g * 16 + 2 * r) =
                    make_float2(e0 + o0 + b0, e1 + o1 + b1);
            }
    }
}

extern "C" void kernel_launch(void* const* d_in, const int* in_sizes, int n_in,
                              void* d_out, int out_size) {
    const float* feat = (const float*)d_in[0];
    const float* wgt  = (const float*)d_in[1];
    const float* bias = (const float*)d_in[2];
    const int*   nbr  = (const int*)d_in[3];
    float* out = (float*)d_out;

    cudaFuncSetAttribute(subm_conv_kernel,
                         cudaFuncAttributeMaxDynamicSharedMemorySize, SMEM_BYTES);
    subm_conv_kernel<<<148, NTHR, SMEM_BYTES>>>(feat, wgt, bias, nbr, out);
}